// round 1
// baseline (speedup 1.0000x reference)
#include <cuda_runtime.h>
#include <math.h>

// ---------------- problem constants ----------------
#define cL    64
#define cEMB  128
#define cH2   128
#define cG3   384      /* 3*H2 */
#define cEXC  256
#define cHID  256
#define cN    200000
#define cK    10

#define OUT_PRED 0L
#define OUT_EXCS 1L
#define OUT_HS   (1L + (long)(cN + 1) * cEXC)   /* 51200257 */

#define K2B   296                 /* blocks in gemv/topk kernel */
#define NCAND (K2B * cK)          /* 2960 candidates */

// ---------------- device scratch (no allocs allowed) ----------------
__device__ float g_gi[2][cL][cG3];   // precomputed input gates, both dirs
__device__ float g_exc[cEXC];        // max-pooled exercise embedding
__device__ float g_cv[NCAND];        // per-block top-k candidate values
__device__ int   g_ci[NCAND];        // per-block top-k candidate indices

__device__ __forceinline__ float sigmoidf_(float x) {
    return 1.0f / (1.0f + expf(-x));
}

// ============================================================
// K0: gi[dir][s][t] = bih[t] + dot(emb[exec_ids[idx]], Wih[t])
//     dir 0: idx = s ; dir 1: idx = L-1-s   (reversed input)
// grid: 128 blocks (dir*64+s), 384 threads (one per gate output)
// ============================================================
__global__ void gi_kernel(const int* __restrict__ exec_ids,
                          const float* __restrict__ emb,
                          const float* __restrict__ wf_Wih,
                          const float* __restrict__ wf_bih,
                          const float* __restrict__ wb_Wih,
                          const float* __restrict__ wb_bih) {
    __shared__ __align__(16) float xs[cEMB];
    int b = blockIdx.x;
    int dir = b >> 6;
    int s = b & 63;
    int row = dir ? (cL - 1 - s) : s;
    int t = threadIdx.x;

    const float* Wih = dir ? wb_Wih : wf_Wih;
    const float* bih = dir ? wb_bih : wf_bih;

    if (t < 32) {
        int wid = exec_ids[row];
        ((float4*)xs)[t] = ((const float4*)(emb + (long)wid * cEMB))[t];
    }
    __syncthreads();

    const float4* w4 = (const float4*)(Wih + (long)t * cEMB);
    const float4* x4 = (const float4*)xs;
    float a0 = 0.f, a1 = 0.f;
#pragma unroll
    for (int k = 0; k < 32; k += 2) {
        float4 w = w4[k];     float4 x = x4[k];
        a0 += w.x * x.x + w.y * x.y + w.z * x.z + w.w * x.w;
        float4 w2 = w4[k + 1]; float4 x2 = x4[k + 1];
        a1 += w2.x * x2.x + w2.y * x2.y + w2.z * x2.z + w2.w * x2.w;
    }
    g_gi[dir][s][t] = a0 + a1 + bih[t];
}

// ============================================================
// K1 mega: blocks 0,1 = GRU recurrence (one per direction),
//          blocks >=2 = copy hs -> out[OUT_HS ...]
// dynamic smem: Whh (49152 f) + h double buffer (256 f) + gates (384 f)
// ============================================================
#define MEGA_SMEM_FLOATS (cG3 * cH2 + 256 + 384)

__global__ void __launch_bounds__(384, 1)
mega_kernel(const float* __restrict__ hs,
            const float* __restrict__ wf_Whh, const float* __restrict__ wf_bhh,
            const float* __restrict__ wb_Whh, const float* __restrict__ wb_bhh,
            float* __restrict__ out) {
    extern __shared__ float sm[];
    int t = threadIdx.x;

    if (blockIdx.x >= 2) {
        // ---- stream copy hs (N x 256 f32) to out[OUT_HS] (dst 16B-misaligned) ----
        const float4* src = (const float4*)hs;
        float* dst = out + OUT_HS;
        const long total4 = (long)cN * cHID / 4;     // 12,800,000
        long stride = (long)(gridDim.x - 2) * blockDim.x;
        for (long i = (long)(blockIdx.x - 2) * blockDim.x + t; i < total4; i += stride) {
            float4 v = src[i];
            long o = i * 4;
            dst[o + 0] = v.x; dst[o + 1] = v.y; dst[o + 2] = v.z; dst[o + 3] = v.w;
        }
        return;
    }

    // ---- GRU recurrence for direction dir ----
    int dir = blockIdx.x;
    float* Wsh  = sm;                       // [k/4][384] float4 layout
    float* hbuf = sm + cG3 * cH2;           // 2 x 128 (double buffer)
    float* gsh  = hbuf + 256;               // 384 gate values

    const float* Whh = dir ? wb_Whh : wf_Whh;
    const float* bhh = dir ? wb_bhh : wf_bhh;

    // stage Whh into shared, layout W4[kk*384 + t] = Whh[t][4kk..4kk+3]
    for (int idx = t; idx < cG3 * cH2 / 4; idx += blockDim.x) {
        int kk = idx / cG3;
        int tt = idx - kk * cG3;
        ((float4*)Wsh)[idx] = *(const float4*)(Whh + (long)tt * cH2 + kk * 4);
    }
    if (t < cH2) hbuf[t] = 0.0f;
    float bhh_t = bhh[t];
    float hmax = -1e30f;
    __syncthreads();

    const float4* W4 = ((const float4*)Wsh) + t;
    for (int s = 0; s < cL; ++s) {
        const float* gi = g_gi[dir][s];
        float* hcur = hbuf + ((s & 1) ? 128 : 0);
        float* hnxt = hbuf + ((s & 1) ? 0 : 128);
        const float4* h4 = (const float4*)hcur;

        float a0 = 0.f, a1 = 0.f;
#pragma unroll
        for (int kk = 0; kk < 32; kk += 2) {
            float4 w = W4[kk * cG3];        float4 hv = h4[kk];
            a0 += w.x * hv.x + w.y * hv.y + w.z * hv.z + w.w * hv.w;
            float4 w2 = W4[(kk + 1) * cG3]; float4 hv2 = h4[kk + 1];
            a1 += w2.x * hv2.x + w2.y * hv2.y + w2.z * hv2.z + w2.w * hv2.w;
        }
        float gh = a0 + a1 + bhh_t;

        // torch gate order (r, z, n): r,z use gi+gh fused; n keeps gh separate
        float g = (t < 256) ? sigmoidf_(gi[t] + gh) : gh;
        gsh[t] = g;
        __syncthreads();

        if (t < cH2) {
            float r = gsh[t];
            float z = gsh[128 + t];
            float n = tanhf(gi[256 + t] + r * gsh[256 + t]);
            float hn = (1.0f - z) * n + z * hcur[t];
            hnxt[t] = hn;
            hmax = fmaxf(hmax, hn);
        }
        __syncthreads();
    }
    if (t < cH2) g_exc[dir * cH2 + t] = hmax;   // maxpool over time
}

// ============================================================
// K2: fused excs copy + alpha gemv + per-block partial top-10
// grid: K2B x 256 (8 warps), one warp per row (grid-strided)
// ============================================================
__global__ void gemv_topk_kernel(const float* __restrict__ excs,
                                 float* __restrict__ out) {
    __shared__ __align__(16) float exc_sh[cEXC];
    __shared__ float wv[8 * cK];
    __shared__ int   wi[8 * cK];

    int t = threadIdx.x;
    int lane = t & 31;
    int warp = t >> 5;
    if (t < cEXC) exc_sh[t] = g_exc[t];
    __syncthreads();

    float tv[cK]; int ti[cK];
#pragma unroll
    for (int j = 0; j < cK; ++j) { tv[j] = -1e30f; ti[j] = 0; }

    int nw = gridDim.x * 8;
    float* dst = out + OUT_EXCS;
    int c0 = lane * 4;

    for (int r = blockIdx.x * 8 + warp; r < cN; r += nw) {
        const float4* rp = (const float4*)(excs + (long)r * cEXC);
        float4 a = rp[lane];
        float4 b = rp[32 + lane];

        float* d = dst + (long)r * cEXC;   // 16B-misaligned region: scalar stores
        d[c0 + 0] = a.x; d[c0 + 1] = a.y; d[c0 + 2] = a.z; d[c0 + 3] = a.w;
        d[128 + c0 + 0] = b.x; d[128 + c0 + 1] = b.y;
        d[128 + c0 + 2] = b.z; d[128 + c0 + 3] = b.w;

        float p = a.x * exc_sh[c0] + a.y * exc_sh[c0 + 1]
                + a.z * exc_sh[c0 + 2] + a.w * exc_sh[c0 + 3]
                + b.x * exc_sh[128 + c0] + b.y * exc_sh[128 + c0 + 1]
                + b.z * exc_sh[128 + c0 + 2] + b.w * exc_sh[128 + c0 + 3];
#pragma unroll
        for (int off = 16; off; off >>= 1)
            p += __shfl_xor_sync(0xffffffffu, p, off);

        // all lanes hold p (uniform) -> run insertion uniformly, lane0 keeps result
        if (p > tv[cK - 1]) {
            int pos = cK - 1;
#pragma unroll
            for (int j = cK - 1; j > 0; --j) {
                if (tv[j - 1] < p) { tv[j] = tv[j - 1]; ti[j] = ti[j - 1]; pos = j - 1; }
            }
            tv[pos] = p; ti[pos] = r;
        }
    }

    if (lane == 0) {
#pragma unroll
        for (int j = 0; j < cK; ++j) { wv[warp * cK + j] = tv[j]; wi[warp * cK + j] = ti[j]; }
    }
    __syncthreads();

    if (t == 0) {
        // merge 8 sorted-10 lists -> block top-10 by selection
        for (int j = 0; j < cK; ++j) {
            float bv = -2e30f; int bm = 0;
            for (int m = 0; m < 8 * cK; ++m)
                if (wv[m] > bv) { bv = wv[m]; bm = m; }
            g_cv[blockIdx.x * cK + j] = bv;
            g_ci[blockIdx.x * cK + j] = wi[bm];
            wv[bm] = -3e30f;
        }
    }
}

// ============================================================
// K3: final — global top-10 merge, softmax, attention, pred,
//     single seq-GRU step, append new rows.  1 block x 768 threads.
// ============================================================
__global__ void final_kernel(const float* __restrict__ hs,
                             const float* __restrict__ score,
                             const float* __restrict__ s_Wih,
                             const float* __restrict__ s_Whh,
                             const float* __restrict__ s_bih,
                             const float* __restrict__ s_bhh,
                             const float* __restrict__ out_W,
                             const float* __restrict__ out_b,
                             float* __restrict__ out) {
    __shared__ float cv[NCAND];
    __shared__ int   ci[NCAND];
    __shared__ float mv[768];
    __shared__ int   mi[768];
    __shared__ float topv[cK];
    __shared__ int   topi[cK];
    __shared__ float wgt[cK];
    __shared__ __align__(16) float exc_sh[cEXC];
    __shared__ __align__(16) float xin[2 * cEXC];
    __shared__ __align__(16) float h_sh[cHID];
    __shared__ float attn[cHID];
    __shared__ float ga[768];
    __shared__ float gb[256];
    __shared__ float red[512];

    int t = threadIdx.x;
    for (int i = t; i < NCAND; i += 768) { cv[i] = g_cv[i]; ci[i] = g_ci[i]; }
    if (t < cEXC) exc_sh[t] = g_exc[t];
    if (t < cHID) h_sh[t] = hs[(long)(cN - 1) * cHID + t];
    __syncthreads();

    // ---- global top-10 by repeated parallel argmax ----
    for (int j = 0; j < cK; ++j) {
        float bv = -1e30f; int bi = 0;
        for (int i = t; i < NCAND; i += 768)
            if (cv[i] > bv) { bv = cv[i]; bi = i; }
        mv[t] = bv; mi[t] = bi;
        __syncthreads();
        for (int sft = 512; sft; sft >>= 1) {
            if (t < sft && t + sft < 768) {
                if (mv[t + sft] > mv[t]) { mv[t] = mv[t + sft]; mi[t] = mi[t + sft]; }
            }
            __syncthreads();
        }
        if (t == 0) {
            topv[j] = mv[0];
            topi[j] = ci[mi[0]];
            cv[mi[0]] = -3e30f;
        }
        __syncthreads();
    }

    // ---- softmax over top-k values ----
    if (t == 0) {
        float mx = topv[0];
        float ssum = 0.f;
        for (int j = 0; j < cK; ++j) { wgt[j] = expf(topv[j] - mx); ssum += wgt[j]; }
        for (int j = 0; j < cK; ++j) wgt[j] /= ssum;
    }
    __syncthreads();

    // ---- attention over gathered hs rows ----
    if (t < cHID) {
        float a = 0.f;
#pragma unroll
        for (int j = 0; j < cK; ++j)
            a += wgt[j] * hs[(long)topi[j] * cHID + t];
        attn[t] = a;
    }

    // ---- score-gated duplicated input ----
    float sc = score[0];
    float pos = (sc >= 0.5f) ? 1.0f : 0.0f;
    if (t < cEXC) xin[t] = exc_sh[t] * pos;
    else if (t < 2 * cEXC) xin[t] = exc_sh[t - cEXC] * (1.0f - pos);
    __syncthreads();

    // ---- pred = dot(concat(exc, attn), out_W) + out_b ----
    if (t < 512) {
        float v = (t < cEXC) ? exc_sh[t] : attn[t - cEXC];
        red[t] = v * out_W[t];
    }
    __syncthreads();
    for (int sft = 256; sft; sft >>= 1) {
        if (t < sft) red[t] += red[t + sft];
        __syncthreads();
    }
    if (t == 0) out[OUT_PRED] = red[0] + out_b[0];

    // ---- single seq-GRU step: thread t computes gate t (768 gates) ----
    {
        float giv = s_bih[t];
        const float4* w4 = (const float4*)(s_Wih + (long)t * 512);
        const float4* x4 = (const float4*)xin;
#pragma unroll 8
        for (int k = 0; k < 128; ++k) {
            float4 w = w4[k]; float4 x = x4[k];
            giv += w.x * x.x + w.y * x.y + w.z * x.z + w.w * x.w;
        }
        float ghv = s_bhh[t];
        const float4* v4 = (const float4*)(s_Whh + (long)t * 256);
        const float4* hh4 = (const float4*)h_sh;
#pragma unroll 8
        for (int k = 0; k < 64; ++k) {
            float4 w = v4[k]; float4 x = hh4[k];
            ghv += w.x * x.x + w.y * x.y + w.z * x.z + w.w * x.w;
        }
        if (t < 512) ga[t] = sigmoidf_(giv + ghv);
        else { ga[t] = ghv; gb[t - 512] = giv; }
    }
    __syncthreads();

    if (t < cHID) {
        float r = ga[t];
        float z = ga[256 + t];
        float n = tanhf(gb[t] + r * ga[512 + t]);
        float hn = (1.0f - z) * n + z * h_sh[t];
        out[OUT_HS + (long)cN * cHID + t] = hn;     // hs_new last row
    }
    if (t < cEXC)
        out[OUT_EXCS + (long)cN * cEXC + t] = exc_sh[t];  // excs_new last row
}

// ============================================================
extern "C" void kernel_launch(void* const* d_in, const int* in_sizes, int n_in,
                              void* d_out, int out_size) {
    const int*   exec_ids = (const int*)d_in[0];
    const float* score    = (const float*)d_in[1];
    const float* excs     = (const float*)d_in[2];
    const float* hs       = (const float*)d_in[3];
    const float* emb      = (const float*)d_in[4];
    const float* wf_Wih   = (const float*)d_in[5];
    const float* wf_Whh   = (const float*)d_in[6];
    const float* wf_bih   = (const float*)d_in[7];
    const float* wf_bhh   = (const float*)d_in[8];
    const float* wb_Wih   = (const float*)d_in[9];
    const float* wb_Whh   = (const float*)d_in[10];
    const float* wb_bih   = (const float*)d_in[11];
    const float* wb_bhh   = (const float*)d_in[12];
    const float* s_Wih    = (const float*)d_in[13];
    const float* s_Whh    = (const float*)d_in[14];
    const float* s_bih    = (const float*)d_in[15];
    const float* s_bhh    = (const float*)d_in[16];
    const float* out_W    = (const float*)d_in[17];
    const float* out_b    = (const float*)d_in[18];
    float* out = (float*)d_out;

    const int mega_smem = MEGA_SMEM_FLOATS * sizeof(float);  // 199,168 B
    cudaFuncSetAttribute(mega_kernel,
                         cudaFuncAttributeMaxDynamicSharedMemorySize, mega_smem);

    gi_kernel<<<128, 384>>>(exec_ids, emb, wf_Wih, wf_bih, wb_Wih, wb_bih);
    mega_kernel<<<150, 384, mega_smem>>>(hs, wf_Whh, wf_bhh, wb_Whh, wb_bhh, out);
    gemv_topk_kernel<<<K2B, 256>>>(excs, out);
    final_kernel<<<1, 768>>>(hs, score, s_Wih, s_Whh, s_bih, s_bhh,
                             out_W, out_b, out);
}

// round 2
// speedup vs baseline: 1.4564x; 1.4564x over previous
#include <cuda_runtime.h>
#include <math.h>

// ---------------- problem constants ----------------
#define cL    64
#define cEMB  128
#define cH2   128
#define cG3   384      /* 3*H2 */
#define cEXC  256
#define cHID  256
#define cN    200000
#define cK    10

#define OUT_PRED 0L
#define OUT_EXCS 1L
#define OUT_HS   (1L + (long)(cN + 1) * cEXC)   /* 51200257 */

#define K2B   296                 /* streaming blocks in gemv/topk kernel */
#define GATEB 96                  /* gate blocks appended (768 gates / 8 warps) */
#define NCAND (K2B * cK)          /* 2960 candidates */

// ---------------- device scratch (no allocs allowed) ----------------
__device__ float g_gi[2][cL][cG3];   // precomputed input gates, both dirs
__device__ float g_exc[cEXC];        // max-pooled exercise embedding
__device__ float g_cv[NCAND];        // per-block top-k candidate values
__device__ int   g_ci[NCAND];        // per-block top-k candidate indices
__device__ float g_giv[3 * cHID];    // seq-GRU input-gate preacts (W_ih@xin + bih)
__device__ float g_ghv[3 * cHID];    // seq-GRU hidden-gate preacts (W_hh@h + bhh)

__device__ __forceinline__ float sigmoidf_(float x) {
    return 1.0f / (1.0f + expf(-x));
}

// ============================================================
// K0: gi[dir][s][t] = bih[t] + dot(emb[exec_ids[idx]], Wih[t])
// ============================================================
__global__ void gi_kernel(const int* __restrict__ exec_ids,
                          const float* __restrict__ emb,
                          const float* __restrict__ wf_Wih,
                          const float* __restrict__ wf_bih,
                          const float* __restrict__ wb_Wih,
                          const float* __restrict__ wb_bih) {
    __shared__ __align__(16) float xs[cEMB];
    int b = blockIdx.x;
    int dir = b >> 6;
    int s = b & 63;
    int row = dir ? (cL - 1 - s) : s;
    int t = threadIdx.x;

    const float* Wih = dir ? wb_Wih : wf_Wih;
    const float* bih = dir ? wb_bih : wf_bih;

    if (t < 32) {
        int wid = exec_ids[row];
        ((float4*)xs)[t] = ((const float4*)(emb + (long)wid * cEMB))[t];
    }
    __syncthreads();

    const float4* w4 = (const float4*)(Wih + (long)t * cEMB);
    const float4* x4 = (const float4*)xs;
    float a0 = 0.f, a1 = 0.f;
#pragma unroll
    for (int k = 0; k < 32; k += 2) {
        float4 w = w4[k];     float4 x = x4[k];
        a0 += w.x * x.x + w.y * x.y + w.z * x.z + w.w * x.w;
        float4 w2 = w4[k + 1]; float4 x2 = x4[k + 1];
        a1 += w2.x * x2.x + w2.y * x2.y + w2.z * x2.z + w2.w * x2.w;
    }
    g_gi[dir][s][t] = a0 + a1 + bih[t];
}

// ============================================================
// K1 mega: blocks 0,1 = GRU recurrence; blocks 2..147 = copy hs
// grid = 148 exactly (one wave @ 1 block/SM due to 199KB smem)
// ============================================================
#define MEGA_SMEM_FLOATS (cG3 * cH2 + 256 + 384)

__global__ void __launch_bounds__(384, 1)
mega_kernel(const float* __restrict__ hs,
            const float* __restrict__ wf_Whh, const float* __restrict__ wf_bhh,
            const float* __restrict__ wb_Whh, const float* __restrict__ wb_bhh,
            float* __restrict__ out) {
    extern __shared__ float sm[];
    int t = threadIdx.x;

    if (blockIdx.x >= 2) {
        // ---- stream copy hs (N x 256 f32) to out[OUT_HS] ----
        // chunk = 4 consecutive float4 per thread-iter (MLP=4)
        const float4* src = (const float4*)hs;
        float* dst = out + OUT_HS;
        const long nchunk = (long)cN * cHID / 16;    // 3,200,000
        long stride = (long)(gridDim.x - 2) * blockDim.x;
        for (long c = (long)(blockIdx.x - 2) * blockDim.x + t; c < nchunk; c += stride) {
            long i = c * 4;
            float4 v0 = src[i];
            float4 v1 = src[i + 1];
            float4 v2 = src[i + 2];
            float4 v3 = src[i + 3];
            long o = i * 4;
            dst[o + 0]  = v0.x; dst[o + 1]  = v0.y; dst[o + 2]  = v0.z; dst[o + 3]  = v0.w;
            dst[o + 4]  = v1.x; dst[o + 5]  = v1.y; dst[o + 6]  = v1.z; dst[o + 7]  = v1.w;
            dst[o + 8]  = v2.x; dst[o + 9]  = v2.y; dst[o + 10] = v2.z; dst[o + 11] = v2.w;
            dst[o + 12] = v3.x; dst[o + 13] = v3.y; dst[o + 14] = v3.z; dst[o + 15] = v3.w;
        }
        return;
    }

    // ---- GRU recurrence for direction dir ----
    int dir = blockIdx.x;
    float* Wsh  = sm;                       // [k/4][384] float4 layout
    float* hbuf = sm + cG3 * cH2;           // 2 x 128 (double buffer)
    float* gsh  = hbuf + 256;               // 384 gate values

    const float* Whh = dir ? wb_Whh : wf_Whh;
    const float* bhh = dir ? wb_bhh : wf_bhh;

    // stage Whh: W4[kk*384 + t] = Whh[t][4kk..4kk+3]
    for (int idx = t; idx < cG3 * cH2 / 4; idx += blockDim.x) {
        int kk = idx / cG3;
        int tt = idx - kk * cG3;
        ((float4*)Wsh)[idx] = *(const float4*)(Whh + (long)tt * cH2 + kk * 4);
    }
    if (t < cH2) hbuf[t] = 0.0f;
    float bhh_t = bhh[t];
    float hmax = -1e30f;
    __syncthreads();

    const float4* W4 = ((const float4*)Wsh) + t;
    for (int s = 0; s < cL; ++s) {
        const float* gi = g_gi[dir][s];
        float* hcur = hbuf + ((s & 1) ? 128 : 0);
        float* hnxt = hbuf + ((s & 1) ? 0 : 128);
        const float4* h4 = (const float4*)hcur;

        float a0 = 0.f, a1 = 0.f;
#pragma unroll
        for (int kk = 0; kk < 32; kk += 2) {
            float4 w = W4[kk * cG3];        float4 hv = h4[kk];
            a0 += w.x * hv.x + w.y * hv.y + w.z * hv.z + w.w * hv.w;
            float4 w2 = W4[(kk + 1) * cG3]; float4 hv2 = h4[kk + 1];
            a1 += w2.x * hv2.x + w2.y * hv2.y + w2.z * hv2.z + w2.w * hv2.w;
        }
        float gh = a0 + a1 + bhh_t;

        float g = (t < 256) ? sigmoidf_(gi[t] + gh) : gh;
        gsh[t] = g;
        __syncthreads();

        if (t < cH2) {
            float r = gsh[t];
            float z = gsh[128 + t];
            float n = tanhf(gi[256 + t] + r * gsh[256 + t]);
            float hn = (1.0f - z) * n + z * hcur[t];
            hnxt[t] = hn;
            hmax = fmaxf(hmax, hn);
        }
        __syncthreads();
    }
    if (t < cH2) g_exc[dir * cH2 + t] = hmax;
}

// ============================================================
// K2: blocks [0, K2B): fused excs copy + alpha gemv + block top-10
//     blocks [K2B, K2B+GATEB): seq-GRU gate preactivations
//       (warp-per-gate, coalesced row reads, zero-half of xin skipped)
// ============================================================
__global__ void gemv_topk_kernel(const float* __restrict__ excs,
                                 const float* __restrict__ hs,
                                 const float* __restrict__ score,
                                 const float* __restrict__ s_Wih,
                                 const float* __restrict__ s_Whh,
                                 const float* __restrict__ s_bih,
                                 const float* __restrict__ s_bhh,
                                 float* __restrict__ out) {
    __shared__ __align__(16) float exc_sh[cEXC];
    __shared__ __align__(16) float h_sh[cHID];
    __shared__ float wv[8 * cK];
    __shared__ int   wi[8 * cK];

    int t = threadIdx.x;
    int lane = t & 31;
    int warp = t >> 5;

    if (blockIdx.x >= K2B) {
        // ---------- gate blocks ----------
        if (t < cEXC) exc_sh[t] = g_exc[t];
        if (t < cHID) h_sh[t] = hs[(long)(cN - 1) * cHID + t];
        __syncthreads();

        int g = (blockIdx.x - K2B) * 8 + warp;   // gate id 0..767
        int off = (score[0] >= 0.5f) ? 0 : 256;  // nonzero half of xin

        const float4* wi4 = (const float4*)(s_Wih + (long)g * 512 + off);
        const float4* wh4 = (const float4*)(s_Whh + (long)g * 256);
        const float4* x4  = (const float4*)exc_sh;
        const float4* hh4 = (const float4*)h_sh;

        float4 a = wi4[lane];       float4 xa = x4[lane];
        float4 b = wi4[lane + 32];  float4 xb = x4[lane + 32];
        float giv = a.x * xa.x + a.y * xa.y + a.z * xa.z + a.w * xa.w
                  + b.x * xb.x + b.y * xb.y + b.z * xb.z + b.w * xb.w;

        float4 c = wh4[lane];       float4 hc = hh4[lane];
        float4 d = wh4[lane + 32];  float4 hd = hh4[lane + 32];
        float ghv = c.x * hc.x + c.y * hc.y + c.z * hc.z + c.w * hc.w
                  + d.x * hd.x + d.y * hd.y + d.z * hd.z + d.w * hd.w;

#pragma unroll
        for (int o = 16; o; o >>= 1) {
            giv += __shfl_xor_sync(0xffffffffu, giv, o);
            ghv += __shfl_xor_sync(0xffffffffu, ghv, o);
        }
        if (lane == 0) {
            g_giv[g] = giv + s_bih[g];
            g_ghv[g] = ghv + s_bhh[g];
        }
        return;
    }

    // ---------- streaming gemv/copy/top-k blocks ----------
    if (t < cEXC) exc_sh[t] = g_exc[t];
    __syncthreads();

    float tv[cK]; int ti[cK];
#pragma unroll
    for (int j = 0; j < cK; ++j) { tv[j] = -1e30f; ti[j] = 0; }

    const int nw = K2B * 8;
    float* dst = out + OUT_EXCS;
    const int c0 = lane * 4;
    const float e0 = exc_sh[c0],       e1 = exc_sh[c0 + 1];
    const float e2 = exc_sh[c0 + 2],   e3 = exc_sh[c0 + 3];
    const float f0 = exc_sh[128 + c0], f1 = exc_sh[128 + c0 + 1];
    const float f2 = exc_sh[128 + c0 + 2], f3 = exc_sh[128 + c0 + 3];

    int r = blockIdx.x * 8 + warp;
    for (; r + nw < cN; r += 2 * nw) {
        const float4* rp1 = (const float4*)(excs + (long)r * cEXC);
        const float4* rp2 = (const float4*)(excs + (long)(r + nw) * cEXC);
        float4 a1 = rp1[lane], b1 = rp1[32 + lane];
        float4 a2 = rp2[lane], b2 = rp2[32 + lane];

        float* d1 = dst + (long)r * cEXC;
        d1[c0 + 0] = a1.x; d1[c0 + 1] = a1.y; d1[c0 + 2] = a1.z; d1[c0 + 3] = a1.w;
        d1[128 + c0 + 0] = b1.x; d1[128 + c0 + 1] = b1.y;
        d1[128 + c0 + 2] = b1.z; d1[128 + c0 + 3] = b1.w;
        float* d2 = dst + (long)(r + nw) * cEXC;
        d2[c0 + 0] = a2.x; d2[c0 + 1] = a2.y; d2[c0 + 2] = a2.z; d2[c0 + 3] = a2.w;
        d2[128 + c0 + 0] = b2.x; d2[128 + c0 + 1] = b2.y;
        d2[128 + c0 + 2] = b2.z; d2[128 + c0 + 3] = b2.w;

        float p1 = a1.x * e0 + a1.y * e1 + a1.z * e2 + a1.w * e3
                 + b1.x * f0 + b1.y * f1 + b1.z * f2 + b1.w * f3;
        float p2 = a2.x * e0 + a2.y * e1 + a2.z * e2 + a2.w * e3
                 + b2.x * f0 + b2.y * f1 + b2.z * f2 + b2.w * f3;
#pragma unroll
        for (int o = 16; o; o >>= 1) {
            p1 += __shfl_xor_sync(0xffffffffu, p1, o);
            p2 += __shfl_xor_sync(0xffffffffu, p2, o);
        }
        if (p1 > tv[cK - 1]) {
            int pos = cK - 1;
#pragma unroll
            for (int j = cK - 1; j > 0; --j)
                if (tv[j - 1] < p1) { tv[j] = tv[j - 1]; ti[j] = ti[j - 1]; pos = j - 1; }
            tv[pos] = p1; ti[pos] = r;
        }
        if (p2 > tv[cK - 1]) {
            int pos = cK - 1;
#pragma unroll
            for (int j = cK - 1; j > 0; --j)
                if (tv[j - 1] < p2) { tv[j] = tv[j - 1]; ti[j] = ti[j - 1]; pos = j - 1; }
            tv[pos] = p2; ti[pos] = r + nw;
        }
    }
    if (r < cN) {
        const float4* rp = (const float4*)(excs + (long)r * cEXC);
        float4 a = rp[lane], b = rp[32 + lane];
        float* d = dst + (long)r * cEXC;
        d[c0 + 0] = a.x; d[c0 + 1] = a.y; d[c0 + 2] = a.z; d[c0 + 3] = a.w;
        d[128 + c0 + 0] = b.x; d[128 + c0 + 1] = b.y;
        d[128 + c0 + 2] = b.z; d[128 + c0 + 3] = b.w;
        float p = a.x * e0 + a.y * e1 + a.z * e2 + a.w * e3
                + b.x * f0 + b.y * f1 + b.z * f2 + b.w * f3;
#pragma unroll
        for (int o = 16; o; o >>= 1) p += __shfl_xor_sync(0xffffffffu, p, o);
        if (p > tv[cK - 1]) {
            int pos = cK - 1;
#pragma unroll
            for (int j = cK - 1; j > 0; --j)
                if (tv[j - 1] < p) { tv[j] = tv[j - 1]; ti[j] = ti[j - 1]; pos = j - 1; }
            tv[pos] = p; ti[pos] = r;
        }
    }

    if (lane == 0) {
#pragma unroll
        for (int j = 0; j < cK; ++j) { wv[warp * cK + j] = tv[j]; wi[warp * cK + j] = ti[j]; }
    }
    __syncthreads();

    if (t == 0) {
        for (int j = 0; j < cK; ++j) {
            float bv = -2e30f; int bm = 0;
            for (int m = 0; m < 8 * cK; ++m)
                if (wv[m] > bv) { bv = wv[m]; bm = m; }
            g_cv[blockIdx.x * cK + j] = bv;
            g_ci[blockIdx.x * cK + j] = wi[bm];
            wv[bm] = -3e30f;
        }
    }
}

// ============================================================
// K3: final — top-10 merge, softmax, attention, pred, GRU combine.
// ============================================================
__global__ void final_kernel(const float* __restrict__ hs,
                             const float* __restrict__ out_W,
                             const float* __restrict__ out_b,
                             float* __restrict__ out) {
    __shared__ float cv[NCAND];
    __shared__ int   ci[NCAND];
    __shared__ float mv[768];
    __shared__ int   mi[768];
    __shared__ float topv[cK];
    __shared__ int   topi[cK];
    __shared__ float wgt[cK];
    __shared__ float exc_sh[cEXC];
    __shared__ float h_sh[cHID];
    __shared__ float attn[cHID];
    __shared__ float red[512];

    int t = threadIdx.x;
    for (int i = t; i < NCAND; i += 768) { cv[i] = g_cv[i]; ci[i] = g_ci[i]; }
    if (t < cEXC) exc_sh[t] = g_exc[t];
    if (t < cHID) h_sh[t] = hs[(long)(cN - 1) * cHID + t];
    __syncthreads();

    // ---- global top-10 by repeated parallel argmax ----
    for (int j = 0; j < cK; ++j) {
        float bv = -1e30f; int bi = 0;
        for (int i = t; i < NCAND; i += 768)
            if (cv[i] > bv) { bv = cv[i]; bi = i; }
        mv[t] = bv; mi[t] = bi;
        __syncthreads();
        for (int sft = 512; sft; sft >>= 1) {
            if (t < sft && t + sft < 768) {
                if (mv[t + sft] > mv[t]) { mv[t] = mv[t + sft]; mi[t] = mi[t + sft]; }
            }
            __syncthreads();
        }
        if (t == 0) {
            topv[j] = mv[0];
            topi[j] = ci[mi[0]];
            cv[mi[0]] = -3e30f;
        }
        __syncthreads();
    }

    if (t == 0) {
        float mx = topv[0];
        float ssum = 0.f;
        for (int j = 0; j < cK; ++j) { wgt[j] = expf(topv[j] - mx); ssum += wgt[j]; }
        for (int j = 0; j < cK; ++j) wgt[j] /= ssum;
    }
    __syncthreads();

    if (t < cHID) {
        float a = 0.f;
#pragma unroll
        for (int j = 0; j < cK; ++j)
            a += wgt[j] * hs[(long)topi[j] * cHID + t];
        attn[t] = a;
    }
    __syncthreads();

    // ---- pred ----
    if (t < 512) {
        float v = (t < cEXC) ? exc_sh[t] : attn[t - cEXC];
        red[t] = v * out_W[t];
    }
    __syncthreads();
    for (int sft = 256; sft; sft >>= 1) {
        if (t < sft) red[t] += red[t + sft];
        __syncthreads();
    }
    if (t == 0) out[OUT_PRED] = red[0] + out_b[0];

    // ---- seq-GRU elementwise combine from precomputed gate preacts ----
    if (t < cHID) {
        float rr = sigmoidf_(g_giv[t] + g_ghv[t]);
        float zz = sigmoidf_(g_giv[cHID + t] + g_ghv[cHID + t]);
        float nn = tanhf(g_giv[2 * cHID + t] + rr * g_ghv[2 * cHID + t]);
        float hn = (1.0f - zz) * nn + zz * h_sh[t];
        out[OUT_HS + (long)cN * cHID + t] = hn;
    }
    if (t < cEXC)
        out[OUT_EXCS + (long)cN * cEXC + t] = exc_sh[t];
}

// ============================================================
extern "C" void kernel_launch(void* const* d_in, const int* in_sizes, int n_in,
                              void* d_out, int out_size) {
    const int*   exec_ids = (const int*)d_in[0];
    const float* score    = (const float*)d_in[1];
    const float* excs     = (const float*)d_in[2];
    const float* hs       = (const float*)d_in[3];
    const float* emb      = (const float*)d_in[4];
    const float* wf_Wih   = (const float*)d_in[5];
    const float* wf_Whh   = (const float*)d_in[6];
    const float* wf_bih   = (const float*)d_in[7];
    const float* wf_bhh   = (const float*)d_in[8];
    const float* wb_Wih   = (const float*)d_in[9];
    const float* wb_Whh   = (const float*)d_in[10];
    const float* wb_bih   = (const float*)d_in[11];
    const float* wb_bhh   = (const float*)d_in[12];
    const float* s_Wih    = (const float*)d_in[13];
    const float* s_Whh    = (const float*)d_in[14];
    const float* s_bih    = (const float*)d_in[15];
    const float* s_bhh    = (const float*)d_in[16];
    const float* out_W    = (const float*)d_in[17];
    const float* out_b    = (const float*)d_in[18];
    float* out = (float*)d_out;

    const int mega_smem = MEGA_SMEM_FLOATS * sizeof(float);  // 199,168 B
    cudaFuncSetAttribute(mega_kernel,
                         cudaFuncAttributeMaxDynamicSharedMemorySize, mega_smem);

    gi_kernel<<<128, 384>>>(exec_ids, emb, wf_Wih, wf_bih, wb_Wih, wb_bih);
    mega_kernel<<<148, 384, mega_smem>>>(hs, wf_Whh, wf_bhh, wb_Whh, wb_bhh, out);
    gemv_topk_kernel<<<K2B + GATEB, 256>>>(excs, hs, score, s_Wih, s_Whh,
                                           s_bih, s_bhh, out);
    final_kernel<<<1, 768>>>(hs, out_W, out_b, out);
}